// round 14
// baseline (speedup 1.0000x reference)
#include <cuda_runtime.h>
#include <cuda_fp16.h>
#include <cstdint>

#define BN_EPS 1e-5f

// ---------------- device scratch ----------------
// g_pclh: fp16 channels-last, channel ci stored at slot sigma(ci):
//   ci<8 : (ci>>1)*4 + (ci&1)
//   ci>=8: ((ci-8)>>1)*4 + 2 + (ci&1)
// so per-thread fp16 MMA fragment halves {2tg,2tg+1,2tg+8,2tg+9} = one 8B word.
__device__ __half        g_pclh[16 * 256 * 256 * 16];
__device__ uint2         g_w2h[9 * 4 * 32];   // conv2 B fragments [tap][nt][lane]
__device__ uint2         g_w1h[3 * 2 * 32];   // conv1 B fragments [ky][nt][lane]
__device__ unsigned char g_mask[256 * 256];
__device__ int           g_count_i;
__device__ float         g_S[16 * 32];
__device__ float         g_bias1[16];
__device__ float         g_bias2[32];

// ---------------- helpers ----------------
__device__ __forceinline__ uint32_t pack2h(float a, float b) {
    __half2 h = __floats2half2_rn(a, b);
    return *(uint32_t*)&h;
}
__device__ __forceinline__ void mma16(float* d, uint32_t a0, uint32_t a1, uint32_t a2,
                                      uint32_t a3, uint32_t b0, uint32_t b1) {
    asm volatile(
        "mma.sync.aligned.m16n8k16.row.col.f32.f16.f16.f32 "
        "{%0,%1,%2,%3},{%4,%5,%6,%7},{%8,%9},{%0,%1,%2,%3};"
        : "+f"(d[0]), "+f"(d[1]), "+f"(d[2]), "+f"(d[3])
        : "r"(a0), "r"(a1), "r"(a2), "r"(a3), "r"(b0), "r"(b1));
}

// ---------------------------------------------------------------------------
// prep: fold BN, build fp16 B-fragments for both convs.
// fp16 m16n8k16 B frag (K16 x N8 col-major), lane (g=lane>>2, tg=lane&3):
//   b0 = {B[2tg][g], B[2tg+1][g]},  b1 = {B[2tg+8][g], B[2tg+9][g]}
// conv1 K index k = dx*4+ci (ci<3, dx<3 valid; else 0). conv2 k = ci.
// ---------------------------------------------------------------------------
__global__ void prep_kernel(const float* __restrict__ w1,
                            const float* __restrict__ g1, const float* __restrict__ b1,
                            const float* __restrict__ m1, const float* __restrict__ v1,
                            const float* __restrict__ w2,
                            const float* __restrict__ g2, const float* __restrict__ b2,
                            const float* __restrict__ m2, const float* __restrict__ v2) {
    int t = threadIdx.x;  // 256
    for (int i = t; i < 512; i += 256) g_S[i] = 0.f;
    if (t == 0) g_count_i = 0;

    if (t < 192) {  // conv1 fragments
        int lane = t & 31, nt = (t >> 5) & 1, ky = t >> 6;
        int g = lane >> 2, tg = lane & 3;
        int n = nt * 8 + g;
        float s = g1[n] * rsqrtf(v1[n] + BN_EPS);
        auto wk = [&](int k) -> float {
            int dx = k >> 2, ci = k & 3;
            return (ci < 3 && dx < 3) ? w1[((n * 3 + ci) * 3 + ky) * 3 + dx] * s : 0.f;
        };
        g_w1h[t] = make_uint2(pack2h(wk(2 * tg), wk(2 * tg + 1)),
                              pack2h(wk(2 * tg + 8), wk(2 * tg + 9)));
    }
    for (int i = t; i < 1152; i += 256) {  // conv2 fragments
        int lane = i & 31, nt = (i >> 5) & 3, tap = i >> 7;
        int g = lane >> 2, tg = lane & 3;
        int ky = tap / 3, kx = tap % 3;
        int n = nt * 8 + g;
        float s = g2[n] * rsqrtf(v2[n] + BN_EPS);
        auto wc = [&](int ci) -> float {
            return w2[((n * 16 + ci) * 3 + ky) * 3 + kx] * s;
        };
        g_w2h[i] = make_uint2(pack2h(wc(2 * tg), wc(2 * tg + 1)),
                              pack2h(wc(2 * tg + 8), wc(2 * tg + 9)));
    }
    if (t < 16) {
        float s = g1[t] * rsqrtf(v1[t] + BN_EPS);
        g_bias1[t] = b1[t] - m1[t] * s;
    }
    if (t < 32) {
        float s = g2[t] * rsqrtf(v2[t] + BN_EPS);
        g_bias2[t] = b2[t] - m2[t] * s;
    }
}

// ---------------------------------------------------------------------------
// K1: conv1(3->16)+bn+relu+maxpool via fp16 mma (K16 = 3dx x 4ci lin im2col).
// CTA = 128 conv px x 16 conv rows (= 64 x 8 pooled). 8 warps x 16 px x 4 rgs.
// Weight fragments hoisted to registers; A-window slides across rgs.
// ---------------------------------------------------------------------------
__global__ __launch_bounds__(256) void k1t_kernel(const float* __restrict__ x) {
    __shared__ __align__(16) __half s_a[18 * 136 * 4];
    __shared__ uint2  s_wf[192];
    __shared__ float  s_b[16];
    __shared__ __align__(16) __half s_out[8 * 64 * 16];

    int b = blockIdx.z, bx = blockIdx.x, by = blockIdx.y;
    int tid = threadIdx.x;

    if (tid < 192) s_wf[tid] = g_w1h[tid];
    if (tid < 16) s_b[tid] = g_bias1[tid];

    int y0 = by * 16, x0 = bx * 128;
    const float* xb = x + (size_t)b * 3 * 262144;
    for (int t = tid; t < 612; t += 256) {  // 18 rows x 34 groups of 4 px
        int r = t / 34, j = t % 34;
        int gy = y0 - 1 + r;
        int gxb = x0 - 4 + 4 * j;
        float4 va = {0.f, 0.f, 0.f, 0.f}, vb = va, vc = va;
        if ((unsigned)gy < 512u) {
            const float* row0 = xb + (size_t)gy * 512;
            if (gxb >= 0 && gxb + 3 < 512) {
                va = *(const float4*)(row0 + gxb);
                vb = *(const float4*)(row0 + 262144 + gxb);
                vc = *(const float4*)(row0 + 524288 + gxb);
            } else {
#pragma unroll
                for (int l = 0; l < 4; l++) {
                    int gx = gxb + l;
                    if ((unsigned)gx < 512u) {
                        (&va.x)[l] = row0[gx];
                        (&vb.x)[l] = row0[262144 + gx];
                        (&vc.x)[l] = row0[524288 + gx];
                    }
                }
            }
        }
        uint4* dst = (uint4*)(s_a + (size_t)(r * 136 + 4 * j) * 4);
        uint4 p0, p1;
        p0.x = pack2h(va.x, vb.x); p0.y = pack2h(vc.x, 0.f);
        p0.z = pack2h(va.y, vb.y); p0.w = pack2h(vc.y, 0.f);
        p1.x = pack2h(va.z, vb.z); p1.y = pack2h(vc.z, 0.f);
        p1.z = pack2h(va.w, vb.w); p1.w = pack2h(vc.w, 0.f);
        dst[0] = p0;
        dst[1] = p1;
    }
    __syncthreads();

    int w = tid >> 5, lane = tid & 31, g = lane >> 2, tg = lane & 3;
    int cb = w * 16 + g + 3;
    const uint32_t* s_au = (const uint32_t*)s_a;

    uint2 WV[6];  // [ky*2+nt], hoisted for all rgs
#pragma unroll
    for (int i = 0; i < 6; i++) WV[i] = s_wf[i * 32 + lane];

    uint32_t A[6][4];  // sliding window of 6 input rows
#pragma unroll
    for (int rr = 0; rr < 6; rr++) {
        int base = (rr * 136 + cb) * 2;
        A[rr][0] = s_au[base + tg];
        A[rr][1] = s_au[base + 16 + tg];
        A[rr][2] = s_au[base + tg + 4];
        A[rr][3] = s_au[base + 16 + tg + 4];
    }

#pragma unroll
    for (int rg = 0; rg < 4; rg++) {
        float d[4][2][4];
#pragma unroll
        for (int r = 0; r < 4; r++)
#pragma unroll
            for (int nt = 0; nt < 2; nt++)
#pragma unroll
                for (int j = 0; j < 4; j++) d[r][nt][j] = 0.f;

#pragma unroll
        for (int ky = 0; ky < 3; ky++)
#pragma unroll
            for (int nt = 0; nt < 2; nt++) {
                uint2 wv = WV[ky * 2 + nt];
#pragma unroll
                for (int r = 0; r < 4; r++) {
                    int ri = r + ky;
                    mma16(d[r][nt], A[ri][0], A[ri][1], A[ri][2], A[ri][3], wv.x, wv.y);
                }
            }

        // maxpool 2x2 + bias + relu, stage fp16 channels-permuted
#pragma unroll
        for (int q = 0; q < 2; q++)
#pragma unroll
            for (int nt = 0; nt < 2; nt++) {
                float m[4];
#pragma unroll
                for (int j = 0; j < 4; j++) {
                    float mm = fmaxf(d[2 * q][nt][j], d[2 * q + 1][nt][j]);
                    mm = fmaxf(mm, __shfl_xor_sync(0xffffffffu, mm, 4));
                    m[j] = mm;
                }
                if (!(g & 1)) {
                    int j = g >> 1;
                    int sl0 = tg * 4 + nt * 2;       // sigma(nt*8+2tg)
                    int sl1 = sl0 + 1;                // sigma(nt*8+2tg+1)
                    float b0 = s_b[nt * 8 + 2 * tg], b1 = s_b[nt * 8 + 2 * tg + 1];
                    int base0 = ((rg * 2 + q) * 64 + w * 8 + j) * 16;
                    int base1 = ((rg * 2 + q) * 64 + w * 8 + j + 4) * 16;
                    s_out[base0 + sl0] = __float2half_rn(fmaxf(m[0] + b0, 0.f));
                    s_out[base0 + sl1] = __float2half_rn(fmaxf(m[1] + b1, 0.f));
                    s_out[base1 + sl0] = __float2half_rn(fmaxf(m[2] + b0, 0.f));
                    s_out[base1 + sl1] = __float2half_rn(fmaxf(m[3] + b1, 0.f));
                }
            }

        // slide window: rows rg*4+4..+5 reused, load rg*4+6..+9
        if (rg < 3) {
#pragma unroll
            for (int j = 0; j < 4; j++) {
                A[0][j] = A[4][j];
                A[1][j] = A[5][j];
            }
#pragma unroll
            for (int i = 0; i < 4; i++) {
                int ar = rg * 4 + 6 + i;
                int base = (ar * 136 + cb) * 2;
                A[2 + i][0] = s_au[base + tg];
                A[2 + i][1] = s_au[base + 16 + tg];
                A[2 + i][2] = s_au[base + tg + 4];
                A[2 + i][3] = s_au[base + 16 + tg + 4];
            }
        }
    }
    __syncthreads();

    for (int idx = tid; idx < 1024; idx += 256) {  // 1024 x 16B
        int s2 = idx & 1, ppx = (idx >> 1) & 63, prow = idx >> 7;
        int py = by * 8 + prow, pxg = bx * 64 + ppx;
        ((uint4*)(g_pclh + ((size_t)(b * 256 + py) * 256 + pxg) * 16))[s2] =
            ((const uint4*)s_out)[idx];
    }
}

// ---------------------------------------------------------------------------
// K2: conv2(16->32)+bn+relu via fp16 mma. CTA = 128 px x 4 output rows,
// 8 warps x 16 px x 4 rows. A: 6 input rows x 130 cells x 16 halves.
// Per kx: A loaded once for 6 rows (serves all 4 outputs); wv serves 4 MMAs.
// MODE 0: batch 0 -> mask + count.  MODE 1: masked channel sums.
// ---------------------------------------------------------------------------
template <int MODE>
__global__ __launch_bounds__(256) void k2_kernel(const float* __restrict__ pf_w,
                                                 const float* __restrict__ pf_b) {
    __shared__ __align__(16) __half s_A[6 * 130 * 16];  // 24960 B
    __shared__ uint2  s_wf[1152];                        // 9216 B
    __shared__ float  s_bias[32];
    __shared__ float  s_pf[32];
    __shared__ float  s_red[256];

    int tid = threadIdx.x;
    int c0 = blockIdx.x * 128;
    int y0 = blockIdx.y * 4;
    int b = (MODE == 0) ? 0 : blockIdx.z;

    for (int i = tid; i < 1152; i += 256) s_wf[i] = g_w2h[i];
    if (tid < 32) {
        s_bias[tid] = g_bias2[tid];
        s_pf[tid] = pf_w[tid];
    }

    // A fill: input rows y0-1..y0+4, cells 0..129 (px = c0-1+cell)
    for (int i = tid; i < 1560; i += 256) {  // 6*130*2 uint4
        int row = i / 260, rem = i % 260, cell = rem >> 1, hi = rem & 1;
        int yy = y0 - 1 + row, px = c0 - 1 + cell;
        uint4 v = {0u, 0u, 0u, 0u};
        if ((unsigned)yy < 256u && (unsigned)px < 256u)
            v = ((const uint4*)(g_pclh + ((size_t)(b * 256 + yy) * 256 + px) * 16))[hi];
        ((uint4*)s_A)[i] = v;
    }
    __syncthreads();

    int w = tid >> 5, lane = tid & 31, g = lane >> 2, tg = lane & 3;
    int pxb = w * 16;
    const uint32_t* s_Au = (const uint32_t*)s_A;

    float d[4][4][4];  // [r][nt][j]: j0,1 = px g cols 2tg,2tg+1; j2,3 = px g+8
#pragma unroll
    for (int r = 0; r < 4; r++)
#pragma unroll
        for (int nt = 0; nt < 4; nt++)
#pragma unroll
            for (int j = 0; j < 4; j++) d[r][nt][j] = 0.f;

#pragma unroll
    for (int kx = 0; kx < 3; kx++) {
        int cell = pxb + g + kx;
        uint2 a02[6], a13[6];
#pragma unroll
        for (int s = 0; s < 6; s++) {
            int base = (s * 130 + cell) * 8;
            a02[s] = *(const uint2*)(s_Au + base + 2 * tg);
            a13[s] = *(const uint2*)(s_Au + base + 64 + 2 * tg);  // px +8
        }
#pragma unroll
        for (int ky = 0; ky < 3; ky++) {
#pragma unroll
            for (int nt = 0; nt < 4; nt++) {
                uint2 wv = s_wf[((ky * 3 + kx) * 4 + nt) * 32 + lane];
#pragma unroll
                for (int r = 0; r < 4; r++) {
                    int s = r + ky;
                    mma16(d[r][nt], a02[s].x, a13[s].x, a02[s].y, a13[s].y,
                          wv.x, wv.y);
                }
            }
        }
    }

    if (MODE == 0) {
        float s[4][2];  // [r][px-half]
#pragma unroll
        for (int r = 0; r < 4; r++) { s[r][0] = 0.f; s[r][1] = 0.f; }
#pragma unroll
        for (int r = 0; r < 4; r++)
#pragma unroll
            for (int nt = 0; nt < 4; nt++) {
                float b0n = s_bias[nt * 8 + 2 * tg], b1n = s_bias[nt * 8 + 2 * tg + 1];
                float p0n = s_pf[nt * 8 + 2 * tg], p1n = s_pf[nt * 8 + 2 * tg + 1];
                s[r][0] += fmaxf(d[r][nt][0] + b0n, 0.f) * p0n +
                           fmaxf(d[r][nt][1] + b1n, 0.f) * p1n;
                s[r][1] += fmaxf(d[r][nt][2] + b0n, 0.f) * p0n +
                           fmaxf(d[r][nt][3] + b1n, 0.f) * p1n;
            }
#pragma unroll
        for (int r = 0; r < 4; r++)
#pragma unroll
            for (int h = 0; h < 2; h++) {
                s[r][h] += __shfl_xor_sync(0xffffffffu, s[r][h], 1);
                s[r][h] += __shfl_xor_sync(0xffffffffu, s[r][h], 2);
            }
        int cnt = 0;
        if (tg == 0) {
            float pb = pf_b[0];
#pragma unroll
            for (int r = 0; r < 4; r++) {
                int y = y0 + r;
                int px = c0 + pxb + g;
                unsigned char m0 = (s[r][0] + pb) > 0.f;
                unsigned char m1 = (s[r][1] + pb) > 0.f;
                g_mask[y * 256 + px] = m0;
                g_mask[y * 256 + px + 8] = m1;
                cnt += m0 + m1;
            }
        }
        cnt = __reduce_add_sync(0xffffffffu, cnt);
        if (lane == 0) atomicAdd(&g_count_i, cnt);
    } else {
        float part[4][2];
#pragma unroll
        for (int nt = 0; nt < 4; nt++) { part[nt][0] = 0.f; part[nt][1] = 0.f; }
#pragma unroll
        for (int r = 0; r < 4; r++) {
            int y = y0 + r;
            float mA = (float)g_mask[y * 256 + c0 + pxb + g];
            float mB = (float)g_mask[y * 256 + c0 + pxb + g + 8];
#pragma unroll
            for (int nt = 0; nt < 4; nt++) {
                float b0n = s_bias[nt * 8 + 2 * tg], b1n = s_bias[nt * 8 + 2 * tg + 1];
                part[nt][0] += mA * fmaxf(d[r][nt][0] + b0n, 0.f) +
                               mB * fmaxf(d[r][nt][2] + b0n, 0.f);
                part[nt][1] += mA * fmaxf(d[r][nt][1] + b1n, 0.f) +
                               mB * fmaxf(d[r][nt][3] + b1n, 0.f);
            }
        }
#pragma unroll
        for (int nt = 0; nt < 4; nt++)
#pragma unroll
            for (int h = 0; h < 2; h++) {
#pragma unroll
                for (int off = 4; off <= 16; off <<= 1)
                    part[nt][h] += __shfl_xor_sync(0xffffffffu, part[nt][h], off);
            }
        if (g == 0) {
#pragma unroll
            for (int nt = 0; nt < 4; nt++) {
                s_red[w * 32 + nt * 8 + 2 * tg] = part[nt][0];
                s_red[w * 32 + nt * 8 + 2 * tg + 1] = part[nt][1];
            }
        }
        __syncthreads();
        if (tid < 32) {
            float s = 0.f;
#pragma unroll
            for (int ww = 0; ww < 8; ww++) s += s_red[ww * 32 + tid];
            atomicAdd(&g_S[b * 32 + tid], s);
        }
    }
}

// ---------------------------------------------------------------------------
__global__ void k3_kernel(const float* __restrict__ vw, const float* __restrict__ vb,
                          const float* __restrict__ cw, const float* __restrict__ cb,
                          float* __restrict__ out) {
    __shared__ float s_mean[512];
    __shared__ float s_cm[1280];
    int t = threadIdx.x;  // 256
    int cnt = g_count_i;
    float denom = (float)(cnt > 0 ? cnt : 1);
    float frac = cnt > 0 ? 1.f : 0.f;
    for (int i = t; i < 512; i += 256) s_mean[i] = g_S[i] / denom;
    __syncthreads();
    for (int i = t; i < 16 * 80; i += 256) {
        int b = i / 80, k = i % 80;
        float a = vb[k] * frac;
        const float* wm = vw + k * 32;
        const float* mm = s_mean + b * 32;
#pragma unroll
        for (int c = 0; c < 32; c++) a += mm[c] * wm[c];
        s_cm[i] = a;
    }
    __syncthreads();
    for (int i = t; i < 1280; i += 256) {
        int b = i / 80, j = i % 80;
        float a = cb[j];
        const float* w = cw + j * 80;
        const float* m = s_cm + b * 80;
#pragma unroll
        for (int k = 0; k < 80; k++) a += m[k] * w[k];
        out[i] = a;
    }
}

// ---------------------------------------------------------------------------
extern "C" void kernel_launch(void* const* d_in, const int* in_sizes, int n_in,
                              void* d_out, int out_size) {
    const float* x   = (const float*)d_in[0];
    const float* w1  = (const float*)d_in[1];
    const float* g1  = (const float*)d_in[2];
    const float* b1  = (const float*)d_in[3];
    const float* m1  = (const float*)d_in[4];
    const float* v1  = (const float*)d_in[5];
    const float* w2  = (const float*)d_in[6];
    const float* g2  = (const float*)d_in[7];
    const float* b2  = (const float*)d_in[8];
    const float* m2  = (const float*)d_in[9];
    const float* v2  = (const float*)d_in[10];
    const float* pfw = (const float*)d_in[11];
    const float* pfb = (const float*)d_in[12];
    const float* vw  = (const float*)d_in[13];
    const float* vb  = (const float*)d_in[14];
    const float* cw  = (const float*)d_in[15];
    const float* cb  = (const float*)d_in[16];
    float* out = (float*)d_out;

    prep_kernel<<<1, 256>>>(w1, g1, b1, m1, v1, w2, g2, b2, m2, v2);
    k1t_kernel<<<dim3(4, 32, 16), 256>>>(x);
    k2_kernel<0><<<dim3(2, 64, 1), 256>>>(pfw, pfb);
    k2_kernel<1><<<dim3(2, 64, 16), 256>>>(pfw, pfb);
    k3_kernel<<<1, 256>>>(vw, vb, cw, cb, out);
}

// round 15
// speedup vs baseline: 1.0402x; 1.0402x over previous
#include <cuda_runtime.h>
#include <cuda_fp16.h>
#include <cstdint>

#define BN_EPS 1e-5f

// ---------------- device scratch ----------------
// g_pclh: fp16 channels-last, channel ci stored at slot sigma(ci):
//   ci<8 : (ci>>1)*4 + (ci&1)
//   ci>=8: ((ci-8)>>1)*4 + 2 + (ci&1)
// so per-thread fp16 MMA fragment halves {2tg,2tg+1,2tg+8,2tg+9} = one 8B word.
__device__ __half        g_pclh[16 * 256 * 256 * 16];
__device__ uint2         g_w2h[9 * 4 * 32];   // conv2 B fragments [tap][nt][lane]
__device__ uint2         g_w1h[3 * 2 * 32];   // conv1 B fragments [ky][nt][lane]
__device__ unsigned char g_mask[256 * 256];
__device__ int           g_count_i;
__device__ float         g_S[16 * 32];
__device__ float         g_bias1[16];
__device__ float         g_bias2[32];

// ---------------- helpers ----------------
__device__ __forceinline__ uint32_t pack2h(float a, float b) {
    __half2 h = __floats2half2_rn(a, b);
    return *(uint32_t*)&h;
}
__device__ __forceinline__ void mma16(float* d, uint32_t a0, uint32_t a1, uint32_t a2,
                                      uint32_t a3, uint32_t b0, uint32_t b1) {
    asm volatile(
        "mma.sync.aligned.m16n8k16.row.col.f32.f16.f16.f32 "
        "{%0,%1,%2,%3},{%4,%5,%6,%7},{%8,%9},{%0,%1,%2,%3};"
        : "+f"(d[0]), "+f"(d[1]), "+f"(d[2]), "+f"(d[3])
        : "r"(a0), "r"(a1), "r"(a2), "r"(a3), "r"(b0), "r"(b1));
}

// ---------------------------------------------------------------------------
// prep: fold BN, build fp16 B-fragments for both convs.
// fp16 m16n8k16 B frag (K16 x N8 col-major), lane (g=lane>>2, tg=lane&3):
//   b0 = {B[2tg][g], B[2tg+1][g]},  b1 = {B[2tg+8][g], B[2tg+9][g]}
// conv1 K index k = dx*4+ci (ci<3, dx<3 valid; else 0). conv2 k = ci.
// ---------------------------------------------------------------------------
__global__ void prep_kernel(const float* __restrict__ w1,
                            const float* __restrict__ g1, const float* __restrict__ b1,
                            const float* __restrict__ m1, const float* __restrict__ v1,
                            const float* __restrict__ w2,
                            const float* __restrict__ g2, const float* __restrict__ b2,
                            const float* __restrict__ m2, const float* __restrict__ v2) {
    int t = threadIdx.x;  // 256
    for (int i = t; i < 512; i += 256) g_S[i] = 0.f;
    if (t == 0) g_count_i = 0;

    if (t < 192) {  // conv1 fragments
        int lane = t & 31, nt = (t >> 5) & 1, ky = t >> 6;
        int g = lane >> 2, tg = lane & 3;
        int n = nt * 8 + g;
        float s = g1[n] * rsqrtf(v1[n] + BN_EPS);
        auto wk = [&](int k) -> float {
            int dx = k >> 2, ci = k & 3;
            return (ci < 3 && dx < 3) ? w1[((n * 3 + ci) * 3 + ky) * 3 + dx] * s : 0.f;
        };
        g_w1h[t] = make_uint2(pack2h(wk(2 * tg), wk(2 * tg + 1)),
                              pack2h(wk(2 * tg + 8), wk(2 * tg + 9)));
    }
    for (int i = t; i < 1152; i += 256) {  // conv2 fragments
        int lane = i & 31, nt = (i >> 5) & 3, tap = i >> 7;
        int g = lane >> 2, tg = lane & 3;
        int ky = tap / 3, kx = tap % 3;
        int n = nt * 8 + g;
        float s = g2[n] * rsqrtf(v2[n] + BN_EPS);
        auto wc = [&](int ci) -> float {
            return w2[((n * 16 + ci) * 3 + ky) * 3 + kx] * s;
        };
        g_w2h[i] = make_uint2(pack2h(wc(2 * tg), wc(2 * tg + 1)),
                              pack2h(wc(2 * tg + 8), wc(2 * tg + 9)));
    }
    if (t < 16) {
        float s = g1[t] * rsqrtf(v1[t] + BN_EPS);
        g_bias1[t] = b1[t] - m1[t] * s;
    }
    if (t < 32) {
        float s = g2[t] * rsqrtf(v2[t] + BN_EPS);
        g_bias2[t] = b2[t] - m2[t] * s;
    }
}

// ---------------------------------------------------------------------------
// K1: conv1(3->16)+bn+relu+maxpool via fp16 mma (K16 = 3dx x 4ci lin im2col).
// CTA = 128 conv px x 16 conv rows (= 64 x 8 pooled). 8 warps x 16 px x 4 rgs.
// Weight fragments hoisted to registers; A-window slides across rgs.
// ---------------------------------------------------------------------------
__global__ __launch_bounds__(256) void k1t_kernel(const float* __restrict__ x) {
    __shared__ __align__(16) __half s_a[18 * 136 * 4];
    __shared__ uint2  s_wf[192];
    __shared__ float  s_b[16];
    __shared__ __align__(16) __half s_out[8 * 64 * 16];

    int b = blockIdx.z, bx = blockIdx.x, by = blockIdx.y;
    int tid = threadIdx.x;

    if (tid < 192) s_wf[tid] = g_w1h[tid];
    if (tid < 16) s_b[tid] = g_bias1[tid];

    int y0 = by * 16, x0 = bx * 128;
    const float* xb = x + (size_t)b * 3 * 262144;
    for (int t = tid; t < 612; t += 256) {  // 18 rows x 34 groups of 4 px
        int r = t / 34, j = t % 34;
        int gy = y0 - 1 + r;
        int gxb = x0 - 4 + 4 * j;
        float4 va = {0.f, 0.f, 0.f, 0.f}, vb = va, vc = va;
        if ((unsigned)gy < 512u) {
            const float* row0 = xb + (size_t)gy * 512;
            if (gxb >= 0 && gxb + 3 < 512) {
                va = *(const float4*)(row0 + gxb);
                vb = *(const float4*)(row0 + 262144 + gxb);
                vc = *(const float4*)(row0 + 524288 + gxb);
            } else {
#pragma unroll
                for (int l = 0; l < 4; l++) {
                    int gx = gxb + l;
                    if ((unsigned)gx < 512u) {
                        (&va.x)[l] = row0[gx];
                        (&vb.x)[l] = row0[262144 + gx];
                        (&vc.x)[l] = row0[524288 + gx];
                    }
                }
            }
        }
        uint4* dst = (uint4*)(s_a + (size_t)(r * 136 + 4 * j) * 4);
        uint4 p0, p1;
        p0.x = pack2h(va.x, vb.x); p0.y = pack2h(vc.x, 0.f);
        p0.z = pack2h(va.y, vb.y); p0.w = pack2h(vc.y, 0.f);
        p1.x = pack2h(va.z, vb.z); p1.y = pack2h(vc.z, 0.f);
        p1.z = pack2h(va.w, vb.w); p1.w = pack2h(vc.w, 0.f);
        dst[0] = p0;
        dst[1] = p1;
    }
    __syncthreads();

    int w = tid >> 5, lane = tid & 31, g = lane >> 2, tg = lane & 3;
    int cb = w * 16 + g + 3;
    const uint32_t* s_au = (const uint32_t*)s_a;

    uint2 WV[6];  // [ky*2+nt], hoisted for all rgs
#pragma unroll
    for (int i = 0; i < 6; i++) WV[i] = s_wf[i * 32 + lane];

    uint32_t A[6][4];  // sliding window of 6 input rows
#pragma unroll
    for (int rr = 0; rr < 6; rr++) {
        int base = (rr * 136 + cb) * 2;
        A[rr][0] = s_au[base + tg];
        A[rr][1] = s_au[base + 16 + tg];
        A[rr][2] = s_au[base + tg + 4];
        A[rr][3] = s_au[base + 16 + tg + 4];
    }

#pragma unroll
    for (int rg = 0; rg < 4; rg++) {
        float d[4][2][4];
#pragma unroll
        for (int r = 0; r < 4; r++)
#pragma unroll
            for (int nt = 0; nt < 2; nt++)
#pragma unroll
                for (int j = 0; j < 4; j++) d[r][nt][j] = 0.f;

#pragma unroll
        for (int ky = 0; ky < 3; ky++)
#pragma unroll
            for (int nt = 0; nt < 2; nt++) {
                uint2 wv = WV[ky * 2 + nt];
#pragma unroll
                for (int r = 0; r < 4; r++) {
                    int ri = r + ky;
                    mma16(d[r][nt], A[ri][0], A[ri][1], A[ri][2], A[ri][3], wv.x, wv.y);
                }
            }

        // maxpool 2x2 + bias + relu, stage fp16 channels-permuted
#pragma unroll
        for (int q = 0; q < 2; q++)
#pragma unroll
            for (int nt = 0; nt < 2; nt++) {
                float m[4];
#pragma unroll
                for (int j = 0; j < 4; j++) {
                    float mm = fmaxf(d[2 * q][nt][j], d[2 * q + 1][nt][j]);
                    mm = fmaxf(mm, __shfl_xor_sync(0xffffffffu, mm, 4));
                    m[j] = mm;
                }
                if (!(g & 1)) {
                    int j = g >> 1;
                    int sl0 = tg * 4 + nt * 2;       // sigma(nt*8+2tg)
                    int sl1 = sl0 + 1;                // sigma(nt*8+2tg+1)
                    float b0 = s_b[nt * 8 + 2 * tg], b1 = s_b[nt * 8 + 2 * tg + 1];
                    int base0 = ((rg * 2 + q) * 64 + w * 8 + j) * 16;
                    int base1 = ((rg * 2 + q) * 64 + w * 8 + j + 4) * 16;
                    s_out[base0 + sl0] = __float2half_rn(fmaxf(m[0] + b0, 0.f));
                    s_out[base0 + sl1] = __float2half_rn(fmaxf(m[1] + b1, 0.f));
                    s_out[base1 + sl0] = __float2half_rn(fmaxf(m[2] + b0, 0.f));
                    s_out[base1 + sl1] = __float2half_rn(fmaxf(m[3] + b1, 0.f));
                }
            }

        // slide window: rows rg*4+4..+5 reused, load rg*4+6..+9
        if (rg < 3) {
#pragma unroll
            for (int j = 0; j < 4; j++) {
                A[0][j] = A[4][j];
                A[1][j] = A[5][j];
            }
#pragma unroll
            for (int i = 0; i < 4; i++) {
                int ar = rg * 4 + 6 + i;
                int base = (ar * 136 + cb) * 2;
                A[2 + i][0] = s_au[base + tg];
                A[2 + i][1] = s_au[base + 16 + tg];
                A[2 + i][2] = s_au[base + tg + 4];
                A[2 + i][3] = s_au[base + 16 + tg + 4];
            }
        }
    }
    __syncthreads();

    for (int idx = tid; idx < 1024; idx += 256) {  // 1024 x 16B
        int s2 = idx & 1, ppx = (idx >> 1) & 63, prow = idx >> 7;
        int py = by * 8 + prow, pxg = bx * 64 + ppx;
        ((uint4*)(g_pclh + ((size_t)(b * 256 + py) * 256 + pxg) * 16))[s2] =
            ((const uint4*)s_out)[idx];
    }
}

// ---------------------------------------------------------------------------
// K2: conv2(16->32)+bn+relu via fp16 mma. CTA = 128 px x 2 output rows,
// 8 warps x 16 px. A: 4 input rows x 130 cells x 16 halves. Per kx: A loaded
// once for all 4 input rows (cross-row reuse), wv hoisted across both rows.
// MODE 0: batch 0 -> mask + count.  MODE 1: masked channel sums.
// (R13 configuration: measured 49.0 us, regs 64, occ 46%.)
// ---------------------------------------------------------------------------
template <int MODE>
__global__ __launch_bounds__(256) void k2_kernel(const float* __restrict__ pf_w,
                                                 const float* __restrict__ pf_b) {
    __shared__ __align__(16) __half s_A[4 * 130 * 16];  // 16640 B
    __shared__ uint2  s_wf[1152];                        // 9216 B
    __shared__ float  s_bias[32];
    __shared__ float  s_pf[32];
    __shared__ float  s_red[256];

    int tid = threadIdx.x;
    int c0 = blockIdx.x * 128;
    int y0 = blockIdx.y * 2;
    int b = (MODE == 0) ? 0 : blockIdx.z;

    for (int i = tid; i < 1152; i += 256) s_wf[i] = g_w2h[i];
    if (tid < 32) {
        s_bias[tid] = g_bias2[tid];
        s_pf[tid] = pf_w[tid];
    }

    // A fill: input rows y0-1..y0+2, cells 0..129 (px = c0-1+cell)
    for (int i = tid; i < 1040; i += 256) {  // 4*130*2 uint4
        int row = i / 260, rem = i % 260, cell = rem >> 1, hi = rem & 1;
        int yy = y0 - 1 + row, px = c0 - 1 + cell;
        uint4 v = {0u, 0u, 0u, 0u};
        if ((unsigned)yy < 256u && (unsigned)px < 256u)
            v = ((const uint4*)(g_pclh + ((size_t)(b * 256 + yy) * 256 + px) * 16))[hi];
        ((uint4*)s_A)[i] = v;
    }
    __syncthreads();

    int w = tid >> 5, lane = tid & 31, g = lane >> 2, tg = lane & 3;
    int pxb = w * 16;
    const uint32_t* s_Au = (const uint32_t*)s_A;

    float d[2][4][4];  // [r][nt][j]: j0,1 = px g cols 2tg,2tg+1; j2,3 = px g+8
#pragma unroll
    for (int r = 0; r < 2; r++)
#pragma unroll
        for (int nt = 0; nt < 4; nt++)
#pragma unroll
            for (int j = 0; j < 4; j++) d[r][nt][j] = 0.f;

#pragma unroll
    for (int kx = 0; kx < 3; kx++) {
        int cell = pxb + g + kx;
        uint2 a02[4], a13[4];
#pragma unroll
        for (int s = 0; s < 4; s++) {
            int base = (s * 130 + cell) * 8;
            a02[s] = *(const uint2*)(s_Au + base + 2 * tg);
            a13[s] = *(const uint2*)(s_Au + base + 64 + 2 * tg);  // px +8
        }
#pragma unroll
        for (int ky = 0; ky < 3; ky++) {
#pragma unroll
            for (int nt = 0; nt < 4; nt++) {
                uint2 wv = s_wf[((ky * 3 + kx) * 4 + nt) * 32 + lane];
                mma16(d[0][nt], a02[ky].x, a13[ky].x, a02[ky].y, a13[ky].y,
                      wv.x, wv.y);
                mma16(d[1][nt], a02[ky + 1].x, a13[ky + 1].x, a02[ky + 1].y,
                      a13[ky + 1].y, wv.x, wv.y);
            }
        }
    }

    if (MODE == 0) {
        float s[2][2] = {{0.f, 0.f}, {0.f, 0.f}};  // [r][px-half]
#pragma unroll
        for (int r = 0; r < 2; r++)
#pragma unroll
            for (int nt = 0; nt < 4; nt++) {
                float b0n = s_bias[nt * 8 + 2 * tg], b1n = s_bias[nt * 8 + 2 * tg + 1];
                float p0n = s_pf[nt * 8 + 2 * tg], p1n = s_pf[nt * 8 + 2 * tg + 1];
                s[r][0] += fmaxf(d[r][nt][0] + b0n, 0.f) * p0n +
                           fmaxf(d[r][nt][1] + b1n, 0.f) * p1n;
                s[r][1] += fmaxf(d[r][nt][2] + b0n, 0.f) * p0n +
                           fmaxf(d[r][nt][3] + b1n, 0.f) * p1n;
            }
#pragma unroll
        for (int r = 0; r < 2; r++)
#pragma unroll
            for (int h = 0; h < 2; h++) {
                s[r][h] += __shfl_xor_sync(0xffffffffu, s[r][h], 1);
                s[r][h] += __shfl_xor_sync(0xffffffffu, s[r][h], 2);
            }
        int cnt = 0;
        if (tg == 0) {
            float pb = pf_b[0];
#pragma unroll
            for (int r = 0; r < 2; r++) {
                int y = y0 + r;
                int px = c0 + pxb + g;
                unsigned char m0 = (s[r][0] + pb) > 0.f;
                unsigned char m1 = (s[r][1] + pb) > 0.f;
                g_mask[y * 256 + px] = m0;
                g_mask[y * 256 + px + 8] = m1;
                cnt += m0 + m1;
            }
        }
        cnt = __reduce_add_sync(0xffffffffu, cnt);
        if (lane == 0) atomicAdd(&g_count_i, cnt);
    } else {
        float part[4][2];
#pragma unroll
        for (int nt = 0; nt < 4; nt++) { part[nt][0] = 0.f; part[nt][1] = 0.f; }
#pragma unroll
        for (int r = 0; r < 2; r++) {
            int y = y0 + r;
            float mA = (float)g_mask[y * 256 + c0 + pxb + g];
            float mB = (float)g_mask[y * 256 + c0 + pxb + g + 8];
#pragma unroll
            for (int nt = 0; nt < 4; nt++) {
                float b0n = s_bias[nt * 8 + 2 * tg], b1n = s_bias[nt * 8 + 2 * tg + 1];
                part[nt][0] += mA * fmaxf(d[r][nt][0] + b0n, 0.f) +
                               mB * fmaxf(d[r][nt][2] + b0n, 0.f);
                part[nt][1] += mA * fmaxf(d[r][nt][1] + b1n, 0.f) +
                               mB * fmaxf(d[r][nt][3] + b1n, 0.f);
            }
        }
#pragma unroll
        for (int nt = 0; nt < 4; nt++)
#pragma unroll
            for (int h = 0; h < 2; h++) {
#pragma unroll
                for (int off = 4; off <= 16; off <<= 1)
                    part[nt][h] += __shfl_xor_sync(0xffffffffu, part[nt][h], off);
            }
        if (g == 0) {
#pragma unroll
            for (int nt = 0; nt < 4; nt++) {
                s_red[w * 32 + nt * 8 + 2 * tg] = part[nt][0];
                s_red[w * 32 + nt * 8 + 2 * tg + 1] = part[nt][1];
            }
        }
        __syncthreads();
        if (tid < 32) {
            float s = 0.f;
#pragma unroll
            for (int ww = 0; ww < 8; ww++) s += s_red[ww * 32 + tid];
            atomicAdd(&g_S[b * 32 + tid], s);
        }
    }
}

// ---------------------------------------------------------------------------
__global__ void k3_kernel(const float* __restrict__ vw, const float* __restrict__ vb,
                          const float* __restrict__ cw, const float* __restrict__ cb,
                          float* __restrict__ out) {
    __shared__ float s_mean[512];
    __shared__ float s_cm[1280];
    int t = threadIdx.x;  // 256
    int cnt = g_count_i;
    float denom = (float)(cnt > 0 ? cnt : 1);
    float frac = cnt > 0 ? 1.f : 0.f;
    for (int i = t; i < 512; i += 256) s_mean[i] = g_S[i] / denom;
    __syncthreads();
    for (int i = t; i < 16 * 80; i += 256) {
        int b = i / 80, k = i % 80;
        float a = vb[k] * frac;
        const float* wm = vw + k * 32;
        const float* mm = s_mean + b * 32;
#pragma unroll
        for (int c = 0; c < 32; c++) a += mm[c] * wm[c];
        s_cm[i] = a;
    }
    __syncthreads();
    for (int i = t; i < 1280; i += 256) {
        int b = i / 80, j = i % 80;
        float a = cb[j];
        const float* w = cw + j * 80;
        const float* m = s_cm + b * 80;
#pragma unroll
        for (int k = 0; k < 80; k++) a += m[k] * w[k];
        out[i] = a;
    }
}

// ---------------------------------------------------------------------------
extern "C" void kernel_launch(void* const* d_in, const int* in_sizes, int n_in,
                              void* d_out, int out_size) {
    const float* x   = (const float*)d_in[0];
    const float* w1  = (const float*)d_in[1];
    const float* g1  = (const float*)d_in[2];
    const float* b1  = (const float*)d_in[3];
    const float* m1  = (const float*)d_in[4];
    const float* v1  = (const float*)d_in[5];
    const float* w2  = (const float*)d_in[6];
    const float* g2  = (const float*)d_in[7];
    const float* b2  = (const float*)d_in[8];
    const float* m2  = (const float*)d_in[9];
    const float* v2  = (const float*)d_in[10];
    const float* pfw = (const float*)d_in[11];
    const float* pfb = (const float*)d_in[12];
    const float* vw  = (const float*)d_in[13];
    const float* vb  = (const float*)d_in[14];
    const float* cw  = (const float*)d_in[15];
    const float* cb  = (const float*)d_in[16];
    float* out = (float*)d_out;

    prep_kernel<<<1, 256>>>(w1, g1, b1, m1, v1, w2, g2, b2, m2, v2);
    k1t_kernel<<<dim3(4, 32, 16), 256>>>(x);
    k2_kernel<0><<<dim3(2, 128, 1), 256>>>(pfw, pfb);
    k2_kernel<1><<<dim3(2, 128, 16), 256>>>(pfw, pfb);
    k3_kernel<<<1, 256>>>(vw, vb, cw, cb, out);
}

// round 16
// speedup vs baseline: 1.0435x; 1.0032x over previous
#include <cuda_runtime.h>
#include <cuda_fp16.h>
#include <cstdint>

#define BN_EPS 1e-5f

// ---------------- device scratch ----------------
// g_pclh: fp16 channels-last, channel ci stored at slot sigma(ci):
//   ci<8 : (ci>>1)*4 + (ci&1)
//   ci>=8: ((ci-8)>>1)*4 + 2 + (ci&1)
// so per-thread fp16 MMA fragment halves {2tg,2tg+1,2tg+8,2tg+9} = one 8B word.
__device__ __half        g_pclh[16 * 256 * 256 * 16];
__device__ uint2         g_w2h[9 * 4 * 32];   // conv2 B fragments [tap][nt][lane]
__device__ uint2         g_w1h[3 * 2 * 32];   // conv1 B fragments [ky][nt][lane]
__device__ unsigned char g_mask[256 * 256];
__device__ int           g_count_i;
__device__ float         g_S[16 * 32];
__device__ float         g_bias1[16];
__device__ float         g_bias2[32];

// ---------------- helpers ----------------
__device__ __forceinline__ uint32_t pack2h(float a, float b) {
    __half2 h = __floats2half2_rn(a, b);
    return *(uint32_t*)&h;
}
__device__ __forceinline__ void mma16(float* d, uint32_t a0, uint32_t a1, uint32_t a2,
                                      uint32_t a3, uint32_t b0, uint32_t b1) {
    asm volatile(
        "mma.sync.aligned.m16n8k16.row.col.f32.f16.f16.f32 "
        "{%0,%1,%2,%3},{%4,%5,%6,%7},{%8,%9},{%0,%1,%2,%3};"
        : "+f"(d[0]), "+f"(d[1]), "+f"(d[2]), "+f"(d[3])
        : "r"(a0), "r"(a1), "r"(a2), "r"(a3), "r"(b0), "r"(b1));
}

// ---------------------------------------------------------------------------
// prep: fold BN, build fp16 B-fragments for both convs.
// fp16 m16n8k16 B frag (K16 x N8 col-major), lane (g=lane>>2, tg=lane&3):
//   b0 = {B[2tg][g], B[2tg+1][g]},  b1 = {B[2tg+8][g], B[2tg+9][g]}
// conv1 K index k = dx*4+ci (ci<3, dx<3 valid; else 0). conv2 k = ci.
// ---------------------------------------------------------------------------
__global__ void prep_kernel(const float* __restrict__ w1,
                            const float* __restrict__ g1, const float* __restrict__ b1,
                            const float* __restrict__ m1, const float* __restrict__ v1,
                            const float* __restrict__ w2,
                            const float* __restrict__ g2, const float* __restrict__ b2,
                            const float* __restrict__ m2, const float* __restrict__ v2) {
    int t = threadIdx.x;  // 256
    for (int i = t; i < 512; i += 256) g_S[i] = 0.f;
    if (t == 0) g_count_i = 0;

    if (t < 192) {  // conv1 fragments
        int lane = t & 31, nt = (t >> 5) & 1, ky = t >> 6;
        int g = lane >> 2, tg = lane & 3;
        int n = nt * 8 + g;
        float s = g1[n] * rsqrtf(v1[n] + BN_EPS);
        auto wk = [&](int k) -> float {
            int dx = k >> 2, ci = k & 3;
            return (ci < 3 && dx < 3) ? w1[((n * 3 + ci) * 3 + ky) * 3 + dx] * s : 0.f;
        };
        g_w1h[t] = make_uint2(pack2h(wk(2 * tg), wk(2 * tg + 1)),
                              pack2h(wk(2 * tg + 8), wk(2 * tg + 9)));
    }
    for (int i = t; i < 1152; i += 256) {  // conv2 fragments
        int lane = i & 31, nt = (i >> 5) & 3, tap = i >> 7;
        int g = lane >> 2, tg = lane & 3;
        int ky = tap / 3, kx = tap % 3;
        int n = nt * 8 + g;
        float s = g2[n] * rsqrtf(v2[n] + BN_EPS);
        auto wc = [&](int ci) -> float {
            return w2[((n * 16 + ci) * 3 + ky) * 3 + kx] * s;
        };
        g_w2h[i] = make_uint2(pack2h(wc(2 * tg), wc(2 * tg + 1)),
                              pack2h(wc(2 * tg + 8), wc(2 * tg + 9)));
    }
    if (t < 16) {
        float s = g1[t] * rsqrtf(v1[t] + BN_EPS);
        g_bias1[t] = b1[t] - m1[t] * s;
    }
    if (t < 32) {
        float s = g2[t] * rsqrtf(v2[t] + BN_EPS);
        g_bias2[t] = b2[t] - m2[t] * s;
    }
}

// ---------------------------------------------------------------------------
// K1: conv1(3->16)+bn+relu+maxpool via fp16 mma (K16 = 3dx x 4ci lin im2col).
// CTA = 128 conv px x 16 conv rows (= 64 x 8 pooled). 8 warps x 16 px x 4 rgs.
// Weight fragments hoisted to registers; A-window slides across rgs.
// Fill specialized: interior CTAs take an unguarded, unrolled path.
// ---------------------------------------------------------------------------
__global__ __launch_bounds__(256) void k1t_kernel(const float* __restrict__ x) {
    __shared__ __align__(16) __half s_a[18 * 136 * 4];
    __shared__ uint2  s_wf[192];
    __shared__ float  s_b[16];
    __shared__ __align__(16) __half s_out[8 * 64 * 16];

    int b = blockIdx.z, bx = blockIdx.x, by = blockIdx.y;
    int tid = threadIdx.x;

    if (tid < 192) s_wf[tid] = g_w1h[tid];
    if (tid < 16) s_b[tid] = g_bias1[tid];

    int y0 = by * 16, x0 = bx * 128;
    const float* xb = x + (size_t)b * 3 * 262144;
    bool interior = (by > 0) & (by < 31) & (bx > 0) & (bx < 3);

    if (interior) {
#pragma unroll
        for (int it = 0; it < 3; it++) {
            int t = tid + it * 256;
            if (t < 612) {
                int r = t / 34, j = t - r * 34;
                const float* row0 = xb + (size_t)(y0 - 1 + r) * 512 + (x0 - 4 + 4 * j);
                float4 va = *(const float4*)(row0);
                float4 vb = *(const float4*)(row0 + 262144);
                float4 vc = *(const float4*)(row0 + 524288);
                uint4* dst = (uint4*)(s_a + (size_t)(r * 136 + 4 * j) * 4);
                uint4 p0, p1;
                p0.x = pack2h(va.x, vb.x); p0.y = pack2h(vc.x, 0.f);
                p0.z = pack2h(va.y, vb.y); p0.w = pack2h(vc.y, 0.f);
                p1.x = pack2h(va.z, vb.z); p1.y = pack2h(vc.z, 0.f);
                p1.z = pack2h(va.w, vb.w); p1.w = pack2h(vc.w, 0.f);
                dst[0] = p0;
                dst[1] = p1;
            }
        }
    } else {
        for (int t = tid; t < 612; t += 256) {  // 18 rows x 34 groups of 4 px
            int r = t / 34, j = t - r * 34;
            int gy = y0 - 1 + r;
            int gxb = x0 - 4 + 4 * j;
            float4 va = {0.f, 0.f, 0.f, 0.f}, vb = va, vc = va;
            if ((unsigned)gy < 512u) {
                const float* row0 = xb + (size_t)gy * 512;
                if (gxb >= 0 && gxb + 3 < 512) {
                    va = *(const float4*)(row0 + gxb);
                    vb = *(const float4*)(row0 + 262144 + gxb);
                    vc = *(const float4*)(row0 + 524288 + gxb);
                } else {
#pragma unroll
                    for (int l = 0; l < 4; l++) {
                        int gx = gxb + l;
                        if ((unsigned)gx < 512u) {
                            (&va.x)[l] = row0[gx];
                            (&vb.x)[l] = row0[262144 + gx];
                            (&vc.x)[l] = row0[524288 + gx];
                        }
                    }
                }
            }
            uint4* dst = (uint4*)(s_a + (size_t)(r * 136 + 4 * j) * 4);
            uint4 p0, p1;
            p0.x = pack2h(va.x, vb.x); p0.y = pack2h(vc.x, 0.f);
            p0.z = pack2h(va.y, vb.y); p0.w = pack2h(vc.y, 0.f);
            p1.x = pack2h(va.z, vb.z); p1.y = pack2h(vc.z, 0.f);
            p1.z = pack2h(va.w, vb.w); p1.w = pack2h(vc.w, 0.f);
            dst[0] = p0;
            dst[1] = p1;
        }
    }
    __syncthreads();

    int w = tid >> 5, lane = tid & 31, g = lane >> 2, tg = lane & 3;
    int cb = w * 16 + g + 3;
    const uint32_t* s_au = (const uint32_t*)s_a;

    uint2 WV[6];  // [ky*2+nt], hoisted for all rgs
#pragma unroll
    for (int i = 0; i < 6; i++) WV[i] = s_wf[i * 32 + lane];

    uint32_t A[6][4];  // sliding window of 6 input rows
#pragma unroll
    for (int rr = 0; rr < 6; rr++) {
        int base = (rr * 136 + cb) * 2;
        A[rr][0] = s_au[base + tg];
        A[rr][1] = s_au[base + 16 + tg];
        A[rr][2] = s_au[base + tg + 4];
        A[rr][3] = s_au[base + 16 + tg + 4];
    }

#pragma unroll
    for (int rg = 0; rg < 4; rg++) {
        float d[4][2][4];
#pragma unroll
        for (int r = 0; r < 4; r++)
#pragma unroll
            for (int nt = 0; nt < 2; nt++)
#pragma unroll
                for (int j = 0; j < 4; j++) d[r][nt][j] = 0.f;

#pragma unroll
        for (int ky = 0; ky < 3; ky++)
#pragma unroll
            for (int nt = 0; nt < 2; nt++) {
                uint2 wv = WV[ky * 2 + nt];
#pragma unroll
                for (int r = 0; r < 4; r++) {
                    int ri = r + ky;
                    mma16(d[r][nt], A[ri][0], A[ri][1], A[ri][2], A[ri][3], wv.x, wv.y);
                }
            }

        // maxpool 2x2 + bias + relu, stage fp16 channels-permuted
#pragma unroll
        for (int q = 0; q < 2; q++)
#pragma unroll
            for (int nt = 0; nt < 2; nt++) {
                float m[4];
#pragma unroll
                for (int j = 0; j < 4; j++) {
                    float mm = fmaxf(d[2 * q][nt][j], d[2 * q + 1][nt][j]);
                    mm = fmaxf(mm, __shfl_xor_sync(0xffffffffu, mm, 4));
                    m[j] = mm;
                }
                if (!(g & 1)) {
                    int j = g >> 1;
                    int sl0 = tg * 4 + nt * 2;       // sigma(nt*8+2tg)
                    int sl1 = sl0 + 1;                // sigma(nt*8+2tg+1)
                    float b0 = s_b[nt * 8 + 2 * tg], b1 = s_b[nt * 8 + 2 * tg + 1];
                    int base0 = ((rg * 2 + q) * 64 + w * 8 + j) * 16;
                    int base1 = ((rg * 2 + q) * 64 + w * 8 + j + 4) * 16;
                    s_out[base0 + sl0] = __float2half_rn(fmaxf(m[0] + b0, 0.f));
                    s_out[base0 + sl1] = __float2half_rn(fmaxf(m[1] + b1, 0.f));
                    s_out[base1 + sl0] = __float2half_rn(fmaxf(m[2] + b0, 0.f));
                    s_out[base1 + sl1] = __float2half_rn(fmaxf(m[3] + b1, 0.f));
                }
            }

        // slide window: rows rg*4+4..+5 reused, load rg*4+6..+9
        if (rg < 3) {
#pragma unroll
            for (int j = 0; j < 4; j++) {
                A[0][j] = A[4][j];
                A[1][j] = A[5][j];
            }
#pragma unroll
            for (int i = 0; i < 4; i++) {
                int ar = rg * 4 + 6 + i;
                int base = (ar * 136 + cb) * 2;
                A[2 + i][0] = s_au[base + tg];
                A[2 + i][1] = s_au[base + 16 + tg];
                A[2 + i][2] = s_au[base + tg + 4];
                A[2 + i][3] = s_au[base + 16 + tg + 4];
            }
        }
    }
    __syncthreads();

    for (int idx = tid; idx < 1024; idx += 256) {  // 1024 x 16B
        int s2 = idx & 1, ppx = (idx >> 1) & 63, prow = idx >> 7;
        int py = by * 8 + prow, pxg = bx * 64 + ppx;
        ((uint4*)(g_pclh + ((size_t)(b * 256 + py) * 256 + pxg) * 16))[s2] =
            ((const uint4*)s_out)[idx];
    }
}

// ---------------------------------------------------------------------------
// K2: conv2(16->32)+bn+relu via fp16 mma. CTA = 128 px x 2 output rows,
// 8 warps x 16 px. A: 4 input rows x 130 cells x 16 halves.
// MODE 0: batch 0 -> mask + count AND batch-0 masked channel sums (mask is
//         locally computable after the score reduction).
// MODE 1: masked channel sums for batches 1..15 (b = blockIdx.z + 1).
// ---------------------------------------------------------------------------
template <int MODE>
__global__ __launch_bounds__(256) void k2_kernel(const float* __restrict__ pf_w,
                                                 const float* __restrict__ pf_b) {
    __shared__ __align__(16) __half s_A[4 * 130 * 16];  // 16640 B
    __shared__ uint2  s_wf[1152];                        // 9216 B
    __shared__ float  s_bias[32];
    __shared__ float  s_pf[32];
    __shared__ float  s_red[256];

    int tid = threadIdx.x;
    int c0 = blockIdx.x * 128;
    int y0 = blockIdx.y * 2;
    int b = (MODE == 0) ? 0 : (blockIdx.z + 1);

    for (int i = tid; i < 1152; i += 256) s_wf[i] = g_w2h[i];
    if (tid < 32) {
        s_bias[tid] = g_bias2[tid];
        s_pf[tid] = pf_w[tid];
    }

    // A fill: input rows y0-1..y0+2, cells 0..129 (px = c0-1+cell)
    for (int i = tid; i < 1040; i += 256) {  // 4*130*2 uint4
        int row = i / 260, rem = i % 260, cell = rem >> 1, hi = rem & 1;
        int yy = y0 - 1 + row, px = c0 - 1 + cell;
        uint4 v = {0u, 0u, 0u, 0u};
        if ((unsigned)yy < 256u && (unsigned)px < 256u)
            v = ((const uint4*)(g_pclh + ((size_t)(b * 256 + yy) * 256 + px) * 16))[hi];
        ((uint4*)s_A)[i] = v;
    }
    __syncthreads();

    int w = tid >> 5, lane = tid & 31, g = lane >> 2, tg = lane & 3;
    int pxb = w * 16;
    const uint32_t* s_Au = (const uint32_t*)s_A;

    float d[2][4][4];  // [r][nt][j]: j0,1 = px g cols 2tg,2tg+1; j2,3 = px g+8
#pragma unroll
    for (int r = 0; r < 2; r++)
#pragma unroll
        for (int nt = 0; nt < 4; nt++)
#pragma unroll
            for (int j = 0; j < 4; j++) d[r][nt][j] = 0.f;

#pragma unroll
    for (int kx = 0; kx < 3; kx++) {
        int cell = pxb + g + kx;
        uint2 a02[4], a13[4];
#pragma unroll
        for (int s = 0; s < 4; s++) {
            int base = (s * 130 + cell) * 8;
            a02[s] = *(const uint2*)(s_Au + base + 2 * tg);
            a13[s] = *(const uint2*)(s_Au + base + 64 + 2 * tg);  // px +8
        }
#pragma unroll
        for (int ky = 0; ky < 3; ky++) {
#pragma unroll
            for (int nt = 0; nt < 4; nt++) {
                uint2 wv = s_wf[((ky * 3 + kx) * 4 + nt) * 32 + lane];
                mma16(d[0][nt], a02[ky].x, a13[ky].x, a02[ky].y, a13[ky].y,
                      wv.x, wv.y);
                mma16(d[1][nt], a02[ky + 1].x, a13[ky + 1].x, a02[ky + 1].y,
                      a13[ky + 1].y, wv.x, wv.y);
            }
        }
    }

    float mAv[2], mBv[2];  // per-row masks for px g / px g+8

    if (MODE == 0) {
        float s[2][2] = {{0.f, 0.f}, {0.f, 0.f}};  // [r][px-half]
#pragma unroll
        for (int r = 0; r < 2; r++)
#pragma unroll
            for (int nt = 0; nt < 4; nt++) {
                float b0n = s_bias[nt * 8 + 2 * tg], b1n = s_bias[nt * 8 + 2 * tg + 1];
                float p0n = s_pf[nt * 8 + 2 * tg], p1n = s_pf[nt * 8 + 2 * tg + 1];
                s[r][0] += fmaxf(d[r][nt][0] + b0n, 0.f) * p0n +
                           fmaxf(d[r][nt][1] + b1n, 0.f) * p1n;
                s[r][1] += fmaxf(d[r][nt][2] + b0n, 0.f) * p0n +
                           fmaxf(d[r][nt][3] + b1n, 0.f) * p1n;
            }
#pragma unroll
        for (int r = 0; r < 2; r++)
#pragma unroll
            for (int h = 0; h < 2; h++) {
                s[r][h] += __shfl_xor_sync(0xffffffffu, s[r][h], 1);
                s[r][h] += __shfl_xor_sync(0xffffffffu, s[r][h], 2);
            }
        float pb = pf_b[0];
#pragma unroll
        for (int r = 0; r < 2; r++) {
            mAv[r] = (s[r][0] + pb) > 0.f ? 1.f : 0.f;
            mBv[r] = (s[r][1] + pb) > 0.f ? 1.f : 0.f;
        }
        int cnt = 0;
        if (tg == 0) {
#pragma unroll
            for (int r = 0; r < 2; r++) {
                int y = y0 + r;
                int px = c0 + pxb + g;
                g_mask[y * 256 + px] = (unsigned char)mAv[r];
                g_mask[y * 256 + px + 8] = (unsigned char)mBv[r];
                cnt += (int)mAv[r] + (int)mBv[r];
            }
        }
        cnt = __reduce_add_sync(0xffffffffu, cnt);
        if (lane == 0) atomicAdd(&g_count_i, cnt);
    } else {
#pragma unroll
        for (int r = 0; r < 2; r++) {
            int y = y0 + r;
            mAv[r] = (float)g_mask[y * 256 + c0 + pxb + g];
            mBv[r] = (float)g_mask[y * 256 + c0 + pxb + g + 8];
        }
    }

    // masked channel sums (both modes; MODE 0 contributes batch 0)
    {
        float part[4][2];
#pragma unroll
        for (int nt = 0; nt < 4; nt++) { part[nt][0] = 0.f; part[nt][1] = 0.f; }
#pragma unroll
        for (int r = 0; r < 2; r++) {
            float mA = mAv[r], mB = mBv[r];
#pragma unroll
            for (int nt = 0; nt < 4; nt++) {
                float b0n = s_bias[nt * 8 + 2 * tg], b1n = s_bias[nt * 8 + 2 * tg + 1];
                part[nt][0] += mA * fmaxf(d[r][nt][0] + b0n, 0.f) +
                               mB * fmaxf(d[r][nt][2] + b0n, 0.f);
                part[nt][1] += mA * fmaxf(d[r][nt][1] + b1n, 0.f) +
                               mB * fmaxf(d[r][nt][3] + b1n, 0.f);
            }
        }
#pragma unroll
        for (int nt = 0; nt < 4; nt++)
#pragma unroll
            for (int h = 0; h < 2; h++) {
#pragma unroll
                for (int off = 4; off <= 16; off <<= 1)
                    part[nt][h] += __shfl_xor_sync(0xffffffffu, part[nt][h], off);
            }
        if (g == 0) {
#pragma unroll
            for (int nt = 0; nt < 4; nt++) {
                s_red[w * 32 + nt * 8 + 2 * tg] = part[nt][0];
                s_red[w * 32 + nt * 8 + 2 * tg + 1] = part[nt][1];
            }
        }
        __syncthreads();
        if (tid < 32) {
            float s = 0.f;
#pragma unroll
            for (int ww = 0; ww < 8; ww++) s += s_red[ww * 32 + tid];
            atomicAdd(&g_S[b * 32 + tid], s);
        }
    }
}

// ---------------------------------------------------------------------------
__global__ void k3_kernel(const float* __restrict__ vw, const float* __restrict__ vb,
                          const float* __restrict__ cw, const float* __restrict__ cb,
                          float* __restrict__ out) {
    __shared__ float s_mean[512];
    __shared__ float s_cm[1280];
    int t = threadIdx.x;  // 256
    int cnt = g_count_i;
    float denom = (float)(cnt > 0 ? cnt : 1);
    float frac = cnt > 0 ? 1.f : 0.f;
    for (int i = t; i < 512; i += 256) s_mean[i] = g_S[i] / denom;
    __syncthreads();
    for (int i = t; i < 16 * 80; i += 256) {
        int b = i / 80, k = i % 80;
        float a = vb[k] * frac;
        const float* wm = vw + k * 32;
        const float* mm = s_mean + b * 32;
#pragma unroll
        for (int c = 0; c < 32; c++) a += mm[c] * wm[c];
        s_cm[i] = a;
    }
    __syncthreads();
    for (int i = t; i < 1280; i += 256) {
        int b = i / 80, j = i % 80;
        float a = cb[j];
        const float* w = cw + j * 80;
        const float* m = s_cm + b * 80;
#pragma unroll
        for (int k = 0; k < 80; k++) a += m[k] * w[k];
        out[i] = a;
    }
}

// ---------------------------------------------------------------------------
extern "C" void kernel_launch(void* const* d_in, const int* in_sizes, int n_in,
                              void* d_out, int out_size) {
    const float* x   = (const float*)d_in[0];
    const float* w1  = (const float*)d_in[1];
    const float* g1  = (const float*)d_in[2];
    const float* b1  = (const float*)d_in[3];
    const float* m1  = (const float*)d_in[4];
    const float* v1  = (const float*)d_in[5];
    const float* w2  = (const float*)d_in[6];
    const float* g2  = (const float*)d_in[7];
    const float* b2  = (const float*)d_in[8];
    const float* m2  = (const float*)d_in[9];
    const float* v2  = (const float*)d_in[10];
    const float* pfw = (const float*)d_in[11];
    const float* pfb = (const float*)d_in[12];
    const float* vw  = (const float*)d_in[13];
    const float* vb  = (const float*)d_in[14];
    const float* cw  = (const float*)d_in[15];
    const float* cb  = (const float*)d_in[16];
    float* out = (float*)d_out;

    prep_kernel<<<1, 256>>>(w1, g1, b1, m1, v1, w2, g2, b2, m2, v2);
    k1t_kernel<<<dim3(4, 32, 16), 256>>>(x);
    k2_kernel<0><<<dim3(2, 128, 1), 256>>>(pfw, pfb);
    k2_kernel<1><<<dim3(2, 128, 15), 256>>>(pfw, pfb);
    k3_kernel<<<1, 256>>>(vw, vb, cw, cb, out);
}